// round 6
// baseline (speedup 1.0000x reference)
#include <cuda_runtime.h>
#include <cuda_fp16.h>
#include <cstdint>

#define NN 4096   // nodes
#define DD 128    // embed dim
#define RR 8      // relations
#define OO 128    // out dim
#define BB 4096   // batch

// Scratch: W[r][n][o] = (E @ K[r])[n][o], fp16, 8 MB.
__device__ __half d_W16[RR * (size_t)NN * OO];
// Scratch: S[n][o] = sum_r (adj_r @ W_r)[n][o], fp32, 2 MB.
__device__ float d_S[(size_t)NN * OO];

// ---------------------------------------------------------------------------
// Kernel 0: zero S
// ---------------------------------------------------------------------------
__global__ __launch_bounds__(256) void zero_kernel()
{
    int i = blockIdx.x * 256 + threadIdx.x;
    ((float4*)d_S)[i] = make_float4(0.f, 0.f, 0.f, 0.f);
}

// ---------------------------------------------------------------------------
// Kernel 1: W16[r][n][o] = (E @ K[r])[n][o], fp32 accumulate, fp16 store
// grid: (64 n-tiles, 8 relations), 256 threads
// ---------------------------------------------------------------------------
__global__ __launch_bounds__(256) void w_kernel(
    const float* __restrict__ emb, const float* __restrict__ relk)
{
    __shared__ float Es[64][DD];                    // 32 KB
    const int t = threadIdx.x;
    const int n0 = blockIdx.x * 64;
    const int r = blockIdx.y;

#pragma unroll
    for (int j = 0; j < 8; j++) {
        int id = t + j * 256;
        int row = id >> 5, c = id & 31;
        *(float4*)&Es[row][c * 4] =
            *(const float4*)(emb + (size_t)(n0 + row) * DD + c * 4);
    }
    __syncthreads();

    const int og = t & 31;                          // o = og*4 .. +3
    const int ng = t >> 5;                          // rows ng*8 .. +7
    const float* Kr = relk + (size_t)r * DD * OO;

    float acc[8][4];
#pragma unroll
    for (int i = 0; i < 8; i++)
#pragma unroll
        for (int j = 0; j < 4; j++) acc[i][j] = 0.f;

    for (int d = 0; d < DD; d++) {
        float4 kv = *((const float4*)(Kr + (size_t)d * OO) + og);
#pragma unroll
        for (int i = 0; i < 8; i++) {
            float ev = Es[ng * 8 + i][d];
            acc[i][0] = fmaf(ev, kv.x, acc[i][0]);
            acc[i][1] = fmaf(ev, kv.y, acc[i][1]);
            acc[i][2] = fmaf(ev, kv.z, acc[i][2]);
            acc[i][3] = fmaf(ev, kv.w, acc[i][3]);
        }
    }

    __half* Wr = d_W16 + (size_t)r * NN * OO;
#pragma unroll
    for (int i = 0; i < 8; i++) {
        int n = n0 + ng * 8 + i;
        __half2 h0 = __floats2half2_rn(acc[i][0], acc[i][1]);
        __half2 h1 = __floats2half2_rn(acc[i][2], acc[i][3]);
        __half2* p = (__half2*)(Wr + (size_t)n * OO + og * 4);
        p[0] = h0; p[1] = h1;
    }
}

// ---------------------------------------------------------------------------
// Kernel 2: S[n, o] += sum_k adj[r, n0+n, kbase+k] * W[r][kbase+k][o]
// Tile 128x128, K-chunk 64, DOUBLE-buffered smem, cp.async for B,
// one __syncthreads per chunk. grid: (32, 8, 2 K-halves), 256 thr (8 warps).
// ---------------------------------------------------------------------------
#define BM 128
#define BK 64
#define KSPLIT 2
#define KHALF (NN / KSPLIT)   // 2048
#define KITERS (KHALF / BK)   // 32
#define ASTR (BK + 8)         // 72 halves / row
#define BSTR (OO + 8)         // 136 halves / row
#define A_STAGE (BM * ASTR * 2)   // 18432 B
#define B_STAGE (BK * BSTR * 2)   // 17408 B
#define SG_SMEM (2 * A_STAGE + 2 * B_STAGE)   // 71680 B

__device__ __forceinline__ uint32_t smaddr(const void* p) {
    return (uint32_t)__cvta_generic_to_shared(p);
}
__device__ __forceinline__ void ldsm_x4(uint32_t (&r)[4], uint32_t addr) {
    asm volatile("ldmatrix.sync.aligned.m8n8.x4.shared.b16 {%0,%1,%2,%3}, [%4];"
        : "=r"(r[0]), "=r"(r[1]), "=r"(r[2]), "=r"(r[3]) : "r"(addr));
}
__device__ __forceinline__ void ldsm_x2t(uint32_t (&r)[2], uint32_t addr) {
    asm volatile("ldmatrix.sync.aligned.m8n8.x2.trans.shared.b16 {%0,%1}, [%2];"
        : "=r"(r[0]), "=r"(r[1]) : "r"(addr));
}
__device__ __forceinline__ void mma_16816(float (&c)[4], const uint32_t (&a)[4],
                                          const uint32_t (&b)[2]) {
    asm volatile(
        "mma.sync.aligned.m16n8k16.row.col.f32.f16.f16.f32 "
        "{%0,%1,%2,%3}, {%4,%5,%6,%7}, {%8,%9}, {%0,%1,%2,%3};"
        : "+f"(c[0]), "+f"(c[1]), "+f"(c[2]), "+f"(c[3])
        : "r"(a[0]), "r"(a[1]), "r"(a[2]), "r"(a[3]), "r"(b[0]), "r"(b[1]));
}
__device__ __forceinline__ void cpa16(uint32_t s, const void* g) {
    asm volatile("cp.async.cg.shared.global [%0], [%1], 16;" :: "r"(s), "l"(g));
}
#define CPA_COMMIT() asm volatile("cp.async.commit_group;" ::: "memory")
#define CPA_WAIT0()  asm volatile("cp.async.wait_group 0;" ::: "memory")

__global__ __launch_bounds__(256, 2) void s_gemm(const float* __restrict__ adj)
{
    extern __shared__ __align__(128) char dsm[];
    const uint32_t sb = smaddr(dsm);
    const int t = threadIdx.x;
    const int m0 = blockIdx.x * BM;
    const int r = blockIdx.y;
    const int kbase = blockIdx.z * KHALF;

    // stage base byte offsets in dsm: A0, A1, B0, B1
    const uint32_t AOFF[2] = { sb, sb + A_STAGE };
    char* const ABASE[2] = { dsm, dsm + A_STAGE };
    const uint32_t BOFF[2] = { sb + 2 * A_STAGE, sb + 2 * A_STAGE + B_STAGE };

    const float* adj_r = adj + (size_t)r * NN * NN;
    const __half* Wr = d_W16 + (size_t)r * NN * OO;

    // A: 128 rows x 64 fp32 per chunk -> 2048 float4 slots, 8/thread
    const float* aptr[8]; uint32_t ast[8];
#pragma unroll
    for (int j = 0; j < 8; j++) {
        int id = t + j * 256;
        int arow = id >> 4, ac4 = id & 15;
        aptr[j] = adj_r + (size_t)(m0 + arow) * NN + kbase + ac4 * 4;
        ast[j] = (uint32_t)(arow * ASTR * 2 + ac4 * 8);   // byte offset in stage
    }
    // B: 1024 x 16B per chunk -> 4/thread, cp.async gmem->smem
    const __half* bgp[4]; uint32_t bst[4];
#pragma unroll
    for (int j = 0; j < 4; j++) {
        int id = t + j * 256;
        int brow = id >> 4, bc8 = id & 15;
        bgp[j] = Wr + (size_t)(kbase + brow) * OO + bc8 * 8;
        bst[j] = (uint32_t)(brow * BSTR * 2 + bc8 * 16);
    }

    const int warp = t >> 5, lane = t & 31;
    const int wm = warp >> 2;            // 0..1 -> 64 M rows
    const int wn = warp & 3;             // 0..3 -> 32 N cols

    float acc[4][4][4];
#pragma unroll
    for (int mf = 0; mf < 4; mf++)
#pragma unroll
        for (int nf = 0; nf < 4; nf++)
#pragma unroll
            for (int v = 0; v < 4; v++) acc[mf][nf][v] = 0.f;

    // ldmatrix fragment byte offsets within a stage
    uint32_t a_off[4], b_off[4];
#pragma unroll
    for (int mf = 0; mf < 4; mf++) {
        int row = wm * 64 + mf * 16 + (lane & 15);
        int col = ((lane >> 4) << 3);
        a_off[mf] = (uint32_t)(row * ASTR * 2 + col * 2);
    }
#pragma unroll
    for (int nf = 0; nf < 4; nf++) {
        int row = (lane & 15);
        int col = wn * 32 + nf * 8;
        b_off[nf] = (uint32_t)(row * BSTR * 2 + col * 2);
    }

    float4 areg[8];

    // ---- prologue: chunk 0 into stage 0 ----
#pragma unroll
    for (int j = 0; j < 8; j++) areg[j] = *(const float4*)aptr[j];
#pragma unroll
    for (int j = 0; j < 8; j++) {
        __half2 h0 = __floats2half2_rn(areg[j].x, areg[j].y);
        __half2 h1 = __floats2half2_rn(areg[j].z, areg[j].w);
        uint2 u; u.x = *(uint32_t*)&h0; u.y = *(uint32_t*)&h1;
        *(uint2*)(ABASE[0] + ast[j]) = u;
    }
#pragma unroll
    for (int j = 0; j < 4; j++) cpa16(BOFF[0] + bst[j], bgp[j]);
    CPA_COMMIT();
#pragma unroll
    for (int j = 0; j < 8; j++) areg[j] = *(const float4*)(aptr[j] + BK);
    CPA_WAIT0();
    __syncthreads();

    // ---- main loop: compute stage s, fill stage !s ----
    for (int kt = 0; kt < KITERS; kt++) {
        const int s = kt & 1;
        const int ns = s ^ 1;

        if (kt + 1 < KITERS) {
            // store A(kt+1) (in aregs) into stage !s
#pragma unroll
            for (int j = 0; j < 8; j++) {
                __half2 h0 = __floats2half2_rn(areg[j].x, areg[j].y);
                __half2 h1 = __floats2half2_rn(areg[j].z, areg[j].w);
                uint2 u; u.x = *(uint32_t*)&h0; u.y = *(uint32_t*)&h1;
                *(uint2*)(ABASE[ns] + ast[j]) = u;
            }
            // async-copy B(kt+1) into stage !s
            const size_t bk0 = (size_t)(kt + 1) * BK * OO;
#pragma unroll
            for (int j = 0; j < 4; j++) cpa16(BOFF[ns] + bst[j], bgp[j] + bk0);
            CPA_COMMIT();
        }
        if (kt + 2 < KITERS) {
            const int k0 = (kt + 2) * BK;
#pragma unroll
            for (int j = 0; j < 8; j++) areg[j] = *(const float4*)(aptr[j] + k0);
        }

        // compute on stage s
#pragma unroll
        for (int ks = 0; ks < 4; ks++) {
            uint32_t af[4][4], bf[4][2];
#pragma unroll
            for (int mf = 0; mf < 4; mf++)
                ldsm_x4(af[mf], AOFF[s] + a_off[mf] + ks * 32);
#pragma unroll
            for (int nf = 0; nf < 4; nf++)
                ldsm_x2t(bf[nf], BOFF[s] + b_off[nf] + ks * 16 * BSTR * 2);
#pragma unroll
            for (int mf = 0; mf < 4; mf++)
#pragma unroll
                for (int nf = 0; nf < 4; nf++)
                    mma_16816(acc[mf][nf], af[mf], bf[nf]);
        }

        if (kt + 1 < KITERS) CPA_WAIT0();
        __syncthreads();
    }

    // Epilogue: accumulate this (relation, K-half) partial into S
    const int rbase = m0 + wm * 64 + (lane >> 2);
    const int cbase = wn * 32 + (lane & 3) * 2;
#pragma unroll
    for (int mf = 0; mf < 4; mf++) {
#pragma unroll
        for (int nf = 0; nf < 4; nf++) {
            int rr = rbase + mf * 16;
            int cc = cbase + nf * 8;
            atomicAdd(&d_S[(size_t)rr * OO + cc],           acc[mf][nf][0]);
            atomicAdd(&d_S[(size_t)rr * OO + cc + 1],       acc[mf][nf][1]);
            atomicAdd(&d_S[(size_t)(rr + 8) * OO + cc],     acc[mf][nf][2]);
            atomicAdd(&d_S[(size_t)(rr + 8) * OO + cc + 1], acc[mf][nf][3]);
        }
    }
}

// ---------------------------------------------------------------------------
// Kernel 3: out[branch][m][o] = (e @ self_kernel)[m][o] + S[idx[m]][o]
// grid: (256 row-tiles of 16, 2 branches), 512 threads, 4 rows/thread
// ---------------------------------------------------------------------------
__global__ __launch_bounds__(512) void final_kernel(
    const float* __restrict__ head_e, const float* __restrict__ tail_e,
    const int* __restrict__ head_idx, const int* __restrict__ tail_idx,
    const float* __restrict__ sk, float* __restrict__ out)
{
    __shared__ float Es[16][DD];                    // 8 KB
    __shared__ int idxs[16];
    const int t = threadIdx.x;
    const int n0 = blockIdx.x * 16;
    const int branch = blockIdx.y;
    const float* e = branch ? tail_e : head_e;
    const int* idx = branch ? tail_idx : head_idx;

    {
        int row = t >> 5, c = t & 31;
        *(float4*)&Es[row][c * 4] =
            *(const float4*)(e + (size_t)(n0 + row) * DD + c * 4);
    }
    if (t < 16) idxs[t] = idx[n0 + t];
    __syncthreads();

    const int o = t & 127;
    const int rg = t >> 7;                          // 0..3 -> 4 rows each
    float acc[4] = {0.f, 0.f, 0.f, 0.f};

#pragma unroll 4
    for (int d4 = 0; d4 < DD / 4; d4++) {
        float s0 = sk[(d4 * 4 + 0) * OO + o];
        float s1 = sk[(d4 * 4 + 1) * OO + o];
        float s2 = sk[(d4 * 4 + 2) * OO + o];
        float s3 = sk[(d4 * 4 + 3) * OO + o];
#pragma unroll
        for (int i = 0; i < 4; i++) {
            float4 ev = *(float4*)&Es[rg * 4 + i][d4 * 4];
            acc[i] = fmaf(ev.x, s0, acc[i]);
            acc[i] = fmaf(ev.y, s1, acc[i]);
            acc[i] = fmaf(ev.z, s2, acc[i]);
            acc[i] = fmaf(ev.w, s3, acc[i]);
        }
    }

    float* ob = out + (size_t)branch * BB * OO;
#pragma unroll
    for (int i = 0; i < 4; i++) {
        int row = rg * 4 + i;
        float sv = d_S[(size_t)idxs[row] * OO + o];
        ob[(size_t)(n0 + row) * OO + o] = acc[i] + sv;
    }
}

// ---------------------------------------------------------------------------
extern "C" void kernel_launch(void* const* d_in, const int* in_sizes, int n_in,
                              void* d_out, int out_size)
{
    const float* emb  = (const float*)d_in[0];
    const int*   hidx = (const int*)  d_in[1];
    const float* he   = (const float*)d_in[2];
    const int*   tidx = (const int*)  d_in[3];
    const float* te   = (const float*)d_in[4];
    const float* adj  = (const float*)d_in[5];
    const float* relk = (const float*)d_in[6];
    const float* sk   = (const float*)d_in[7];
    float* out = (float*)d_out;

    static int smem_set = 0;
    if (!smem_set) {
        cudaFuncSetAttribute(s_gemm, cudaFuncAttributeMaxDynamicSharedMemorySize,
                             SG_SMEM);
        smem_set = 1;
    }

    // 0) S = 0
    zero_kernel<<<NN * OO / (256 * 4), 256>>>();
    // 1) W[r] = E @ K[r] in fp32, stored fp16
    w_kernel<<<dim3(NN / 64, RR), 256>>>(emb, relk);
    // 2) S = sum_r adj_r @ W_r   (fp16 mma.sync, double-buffered + cp.async)
    s_gemm<<<dim3(NN / BM, RR, KSPLIT), 256, SG_SMEM>>>(adj);
    // 3) out = e @ self_kernel + gather(S, idx)
    final_kernel<<<dim3(BB / 16, 2), 512>>>(he, te, hidx, tidx, sk, out);
}

// round 8
// speedup vs baseline: 1.2077x; 1.2077x over previous
#include <cuda_runtime.h>
#include <cuda_fp16.h>
#include <cstdint>

#define NN 4096   // nodes
#define DD 128    // embed dim
#define RR 8      // relations
#define OO 128    // out dim
#define BB 4096   // batch
#define ZSPLIT 16 // k-splits in s_gemm

// Scratch: W[r][n][o] = (E @ K[r])[n][o], fp16, 8 MB.
__device__ __half d_W16[RR * (size_t)NN * OO];
// Scratch: partial S per k-split, fp32, 32 MB.
__device__ float d_Spart[ZSPLIT * (size_t)NN * OO];
// Scratch: S[n][o] = sum_z Spart, fp32, 2 MB.
__device__ float d_S[(size_t)NN * OO];

// ---------------------------------------------------------------------------
// MMA helpers (fragment math validated in R2/R6 passing kernels)
// ---------------------------------------------------------------------------
__device__ __forceinline__ uint32_t smaddr(const void* p) {
    return (uint32_t)__cvta_generic_to_shared(p);
}
__device__ __forceinline__ void ldsm_x4(uint32_t (&r)[4], uint32_t addr) {
    asm volatile("ldmatrix.sync.aligned.m8n8.x4.shared.b16 {%0,%1,%2,%3}, [%4];"
        : "=r"(r[0]), "=r"(r[1]), "=r"(r[2]), "=r"(r[3]) : "r"(addr));
}
__device__ __forceinline__ void ldsm_x2t(uint32_t (&r)[2], uint32_t addr) {
    asm volatile("ldmatrix.sync.aligned.m8n8.x2.trans.shared.b16 {%0,%1}, [%2];"
        : "=r"(r[0]), "=r"(r[1]) : "r"(addr));
}
__device__ __forceinline__ void mma_16816(float (&c)[4], const uint32_t (&a)[4],
                                          const uint32_t (&b)[2]) {
    asm volatile(
        "mma.sync.aligned.m16n8k16.row.col.f32.f16.f16.f32 "
        "{%0,%1,%2,%3}, {%4,%5,%6,%7}, {%8,%9}, {%0,%1,%2,%3};"
        : "+f"(c[0]), "+f"(c[1]), "+f"(c[2]), "+f"(c[3])
        : "r"(a[0]), "r"(a[1]), "r"(a[2]), "r"(a[3]), "r"(b[0]), "r"(b[1]));
}
__device__ __forceinline__ void cpa16(uint32_t s, const void* g) {
    asm volatile("cp.async.cg.shared.global [%0], [%1], 16;" :: "r"(s), "l"(g));
}
#define CPA_COMMIT() asm volatile("cp.async.commit_group;" ::: "memory")
#define CPA_WAIT0()  asm volatile("cp.async.wait_group 0;" ::: "memory")

// ---------------------------------------------------------------------------
// Single-shot 128x128x128 fp16 MMA core for w_gemm / out_gemm.
// A (128x128 fp32, row-major) and B (128x128 fp32, k-major [k][n]) are
// converted to fp16 in smem; acc[4][4][4] per thread (8 warps, 2x4).
// ---------------------------------------------------------------------------
#define STR 136                       // halves per smem row (128 + 8 pad)
#define WO_SMEM (2 * 128 * STR * 2)   // 69632 B (A + B)

__device__ __forceinline__ void wo_core(
    const float* __restrict__ Ag, const float* __restrict__ Bg,
    char* dsm, float (&acc)[4][4][4])
{
    const int t = threadIdx.x;
    const uint32_t sb = smaddr(dsm);
    char* As = dsm;
    char* Bs = dsm + 128 * STR * 2;
    const uint32_t AOFF = sb, BOFF = sb + 128 * STR * 2;

#pragma unroll
    for (int j = 0; j < 16; j++) {
        int id = t + j * 256;
        int row = id >> 5, c4 = id & 31;
        float4 v = *(const float4*)(Ag + (size_t)row * 128 + c4 * 4);
        __half2 h0 = __floats2half2_rn(v.x, v.y);
        __half2 h1 = __floats2half2_rn(v.z, v.w);
        uint2 u; u.x = *(uint32_t*)&h0; u.y = *(uint32_t*)&h1;
        *(uint2*)(As + row * STR * 2 + c4 * 8) = u;
    }
#pragma unroll
    for (int j = 0; j < 16; j++) {
        int id = t + j * 256;
        int row = id >> 5, c4 = id & 31;
        float4 v = *(const float4*)(Bg + (size_t)row * 128 + c4 * 4);
        __half2 h0 = __floats2half2_rn(v.x, v.y);
        __half2 h1 = __floats2half2_rn(v.z, v.w);
        uint2 u; u.x = *(uint32_t*)&h0; u.y = *(uint32_t*)&h1;
        *(uint2*)(Bs + row * STR * 2 + c4 * 8) = u;
    }
    __syncthreads();

    const int warp = t >> 5, lane = t & 31;
    const int wm = warp >> 2, wn = warp & 3;

    uint32_t a_off[4], b_off[4];
#pragma unroll
    for (int mf = 0; mf < 4; mf++) {
        int row = wm * 64 + mf * 16 + (lane & 15);
        int col = ((lane >> 4) << 3);
        a_off[mf] = (uint32_t)(row * STR * 2 + col * 2);
    }
#pragma unroll
    for (int nf = 0; nf < 4; nf++) {
        int row = (lane & 15);
        int col = wn * 32 + nf * 8;
        b_off[nf] = (uint32_t)(row * STR * 2 + col * 2);
    }

#pragma unroll
    for (int ks = 0; ks < 8; ks++) {
        uint32_t af[4][4], bf[4][2];
#pragma unroll
        for (int mf = 0; mf < 4; mf++)
            ldsm_x4(af[mf], AOFF + a_off[mf] + ks * 32);
#pragma unroll
        for (int nf = 0; nf < 4; nf++)
            ldsm_x2t(bf[nf], BOFF + b_off[nf] + ks * 16 * STR * 2);
#pragma unroll
        for (int mf = 0; mf < 4; mf++)
#pragma unroll
            for (int nf = 0; nf < 4; nf++)
                mma_16816(acc[mf][nf], af[mf], bf[nf]);
    }
}

// ---------------------------------------------------------------------------
// Kernel 1: W16[r] = fp16(E @ K[r]).  grid (32 m-tiles, 8 relations), 256 thr.
// ---------------------------------------------------------------------------
__global__ __launch_bounds__(256, 2) void w_gemm(
    const float* __restrict__ emb, const float* __restrict__ relk)
{
    extern __shared__ __align__(128) char dsm[];
    const int m0 = blockIdx.x * 128;
    const int r = blockIdx.y;

    float acc[4][4][4];
#pragma unroll
    for (int mf = 0; mf < 4; mf++)
#pragma unroll
        for (int nf = 0; nf < 4; nf++)
#pragma unroll
            for (int v = 0; v < 4; v++) acc[mf][nf][v] = 0.f;

    wo_core(emb + (size_t)m0 * DD, relk + (size_t)r * DD * OO, dsm, acc);

    const int warp = threadIdx.x >> 5, lane = threadIdx.x & 31;
    const int wm = warp >> 2, wn = warp & 3;
    __half* Wr = d_W16 + (size_t)r * NN * OO;
    const int rbase = m0 + wm * 64 + (lane >> 2);
    const int cbase = wn * 32 + (lane & 3) * 2;
#pragma unroll
    for (int mf = 0; mf < 4; mf++)
#pragma unroll
        for (int nf = 0; nf < 4; nf++) {
            int rr = rbase + mf * 16, cc = cbase + nf * 8;
            *(__half2*)(Wr + (size_t)rr * OO + cc) =
                __floats2half2_rn(acc[mf][nf][0], acc[mf][nf][1]);
            *(__half2*)(Wr + (size_t)(rr + 8) * OO + cc) =
                __floats2half2_rn(acc[mf][nf][2], acc[mf][nf][3]);
        }
}

// ---------------------------------------------------------------------------
// Kernel 2: Spart[z][m][o] = sum_{r} sum_{k in z-range} adj[r,m,k] * W[r][k][o]
// Relation loop INSIDE (acc accumulates across r) -> no atomics.
// grid (32 m-tiles, 16 z-splits), 256 threads, double-buffered, cp.async B.
// ---------------------------------------------------------------------------
#define BM 128
#define BK 64
#define KRANGE (NN / ZSPLIT)      // 256 k per CTA per relation
#define QITERS (RR * KRANGE / BK) // 32 chunks total
#define ASTR (BK + 8)
#define BSTR (OO + 8)
#define A_STAGE (BM * ASTR * 2)   // 18432 B
#define B_STAGE (BK * BSTR * 2)   // 17408 B
#define SG_SMEM (2 * A_STAGE + 2 * B_STAGE)   // 71680 B

__global__ __launch_bounds__(256, 2) void s_gemm(const float* __restrict__ adj)
{
    extern __shared__ __align__(128) char dsm[];
    const uint32_t sb = smaddr(dsm);
    const int t = threadIdx.x;
    const int m0 = blockIdx.x * BM;
    const int z = blockIdx.y;
    const int kz = z * KRANGE;

    const uint32_t AOFF[2] = { sb, sb + A_STAGE };
    char* const ABASE[2] = { dsm, dsm + A_STAGE };
    const uint32_t BOFF[2] = { sb + 2 * A_STAGE, sb + 2 * A_STAGE + B_STAGE };

    // A: per-thread base into adj (r=0, kc=0); add uniform q-offset later.
    const float* aptr[8]; uint32_t ast[8];
#pragma unroll
    for (int j = 0; j < 8; j++) {
        int id = t + j * 256;
        int arow = id >> 4, ac4 = id & 15;
        aptr[j] = adj + (size_t)(m0 + arow) * NN + kz + ac4 * 4;
        ast[j] = (uint32_t)(arow * ASTR * 2 + ac4 * 8);
    }
    // B: per-thread base into W (r=0, kc=0)
    const __half* bgp[4]; uint32_t bst[4];
#pragma unroll
    for (int j = 0; j < 4; j++) {
        int id = t + j * 256;
        int brow = id >> 4, bc8 = id & 15;
        bgp[j] = d_W16 + (size_t)(kz + brow) * OO + bc8 * 8;
        bst[j] = (uint32_t)(brow * BSTR * 2 + bc8 * 16);
    }

    const int warp = t >> 5, lane = t & 31;
    const int wm = warp >> 2, wn = warp & 3;

    float acc[4][4][4];
#pragma unroll
    for (int mf = 0; mf < 4; mf++)
#pragma unroll
        for (int nf = 0; nf < 4; nf++)
#pragma unroll
            for (int v = 0; v < 4; v++) acc[mf][nf][v] = 0.f;

    uint32_t a_off[4], b_off[4];
#pragma unroll
    for (int mf = 0; mf < 4; mf++) {
        int row = wm * 64 + mf * 16 + (lane & 15);
        int col = ((lane >> 4) << 3);
        a_off[mf] = (uint32_t)(row * ASTR * 2 + col * 2);
    }
#pragma unroll
    for (int nf = 0; nf < 4; nf++) {
        int row = (lane & 15);
        int col = wn * 32 + nf * 8;
        b_off[nf] = (uint32_t)(row * BSTR * 2 + col * 2);
    }

    // uniform per-chunk offsets: q = r*4 + kc
    auto QA = [](int q) -> size_t {
        return ((size_t)(q >> 2) * (size_t)NN * NN) + (size_t)(q & 3) * BK;
    };
    auto QB = [](int q) -> size_t {
        return ((size_t)(q >> 2) * (size_t)NN * OO) + (size_t)(q & 3) * BK * OO;
    };

    float4 areg[8];

    // prologue: chunk 0 -> stage 0
#pragma unroll
    for (int j = 0; j < 8; j++) areg[j] = *(const float4*)aptr[j];
#pragma unroll
    for (int j = 0; j < 8; j++) {
        __half2 h0 = __floats2half2_rn(areg[j].x, areg[j].y);
        __half2 h1 = __floats2half2_rn(areg[j].z, areg[j].w);
        uint2 u; u.x = *(uint32_t*)&h0; u.y = *(uint32_t*)&h1;
        *(uint2*)(ABASE[0] + ast[j]) = u;
    }
#pragma unroll
    for (int j = 0; j < 4; j++) cpa16(BOFF[0] + bst[j], bgp[j]);
    CPA_COMMIT();
    {
        const size_t o1 = QA(1);
#pragma unroll
        for (int j = 0; j < 8; j++) areg[j] = *(const float4*)(aptr[j] + o1);
    }
    CPA_WAIT0();
    __syncthreads();

    for (int q = 0; q < QITERS; q++) {
        const int s = q & 1, ns = s ^ 1;

        if (q + 1 < QITERS) {
#pragma unroll
            for (int j = 0; j < 8; j++) {
                __half2 h0 = __floats2half2_rn(areg[j].x, areg[j].y);
                __half2 h1 = __floats2half2_rn(areg[j].z, areg[j].w);
                uint2 u; u.x = *(uint32_t*)&h0; u.y = *(uint32_t*)&h1;
                *(uint2*)(ABASE[ns] + ast[j]) = u;
            }
            const size_t ob = QB(q + 1);
#pragma unroll
            for (int j = 0; j < 4; j++) cpa16(BOFF[ns] + bst[j], bgp[j] + ob);
            CPA_COMMIT();
        }
        if (q + 2 < QITERS) {
            const size_t oa = QA(q + 2);
#pragma unroll
            for (int j = 0; j < 8; j++) areg[j] = *(const float4*)(aptr[j] + oa);
        }

#pragma unroll
        for (int ks = 0; ks < 4; ks++) {
            uint32_t af[4][4], bf[4][2];
#pragma unroll
            for (int mf = 0; mf < 4; mf++)
                ldsm_x4(af[mf], AOFF[s] + a_off[mf] + ks * 32);
#pragma unroll
            for (int nf = 0; nf < 4; nf++)
                ldsm_x2t(bf[nf], BOFF[s] + b_off[nf] + ks * 16 * BSTR * 2);
#pragma unroll
            for (int mf = 0; mf < 4; mf++)
#pragma unroll
                for (int nf = 0; nf < 4; nf++)
                    mma_16816(acc[mf][nf], af[mf], bf[nf]);
        }

        if (q + 1 < QITERS) CPA_WAIT0();
        __syncthreads();
    }

    // Epilogue: plain stores into this z-split's partial buffer
    float* Sp = d_Spart + (size_t)z * NN * OO;
    const int rbase = m0 + wm * 64 + (lane >> 2);
    const int cbase = wn * 32 + (lane & 3) * 2;
#pragma unroll
    for (int mf = 0; mf < 4; mf++)
#pragma unroll
        for (int nf = 0; nf < 4; nf++) {
            int rr = rbase + mf * 16, cc = cbase + nf * 8;
            *(float2*)(Sp + (size_t)rr * OO + cc) =
                make_float2(acc[mf][nf][0], acc[mf][nf][1]);
            *(float2*)(Sp + (size_t)(rr + 8) * OO + cc) =
                make_float2(acc[mf][nf][2], acc[mf][nf][3]);
        }
}

// ---------------------------------------------------------------------------
// Kernel 3: S = sum_z Spart[z].  grid 256, 512 threads, float4 each.
// ---------------------------------------------------------------------------
__global__ __launch_bounds__(512) void reduce_kernel()
{
    const size_t i = (size_t)blockIdx.x * 512 + threadIdx.x;   // float4 index
    const float4* p = (const float4*)d_Spart + i;
    float4 s = p[0];
#pragma unroll
    for (int zz = 1; zz < ZSPLIT; zz++) {
        float4 v = p[(size_t)zz * (NN * OO / 4)];
        s.x += v.x; s.y += v.y; s.z += v.z; s.w += v.w;
    }
    ((float4*)d_S)[i] = s;
}

// ---------------------------------------------------------------------------
// Kernel 4: out[m][o] = ([he;te] @ SK)[m][o] + S[idx[m]][o]
// grid 64 m-tiles (8192 rows), 256 threads.
// ---------------------------------------------------------------------------
__global__ __launch_bounds__(256, 2) void out_gemm(
    const float* __restrict__ head_e, const float* __restrict__ tail_e,
    const int* __restrict__ head_idx, const int* __restrict__ tail_idx,
    const float* __restrict__ sk, float* __restrict__ out)
{
    extern __shared__ __align__(128) char dsm[];
    const int m0 = blockIdx.x * 128;
    const int branch = (m0 >= BB);
    const float* e = branch ? (tail_e + (size_t)(m0 - BB) * DD)
                            : (head_e + (size_t)m0 * DD);
    const int* idx = branch ? tail_idx : head_idx;
    const int mloc0 = branch ? m0 - BB : m0;

    float acc[4][4][4];
#pragma unroll
    for (int mf = 0; mf < 4; mf++)
#pragma unroll
        for (int nf = 0; nf < 4; nf++)
#pragma unroll
            for (int v = 0; v < 4; v++) acc[mf][nf][v] = 0.f;

    wo_core(e, sk, dsm, acc);

    const int warp = threadIdx.x >> 5, lane = threadIdx.x & 31;
    const int wm = warp >> 2, wn = warp & 3;
    const int rloc = mloc0 + wm * 64 + (lane >> 2);      // local row in branch
    const int cbase = wn * 32 + (lane & 3) * 2;
#pragma unroll
    for (int mf = 0; mf < 4; mf++) {
        int r0 = rloc + mf * 16;
        int i0 = idx[r0], i1 = idx[r0 + 8];
        const float* S0 = d_S + (size_t)i0 * OO;
        const float* S1 = d_S + (size_t)i1 * OO;
        float* o0 = out + ((size_t)branch * BB + r0) * OO;
        float* o1 = o0 + 8 * OO;
#pragma unroll
        for (int nf = 0; nf < 4; nf++) {
            int cc = cbase + nf * 8;
            float2 s0 = *(const float2*)(S0 + cc);
            float2 s1 = *(const float2*)(S1 + cc);
            *(float2*)(o0 + cc) = make_float2(acc[mf][nf][0] + s0.x,
                                              acc[mf][nf][1] + s0.y);
            *(float2*)(o1 + cc) = make_float2(acc[mf][nf][2] + s1.x,
                                              acc[mf][nf][3] + s1.y);
        }
    }
}

// ---------------------------------------------------------------------------
extern "C" void kernel_launch(void* const* d_in, const int* in_sizes, int n_in,
                              void* d_out, int out_size)
{
    const float* emb  = (const float*)d_in[0];
    const int*   hidx = (const int*)  d_in[1];
    const float* he   = (const float*)d_in[2];
    const int*   tidx = (const int*)  d_in[3];
    const float* te   = (const float*)d_in[4];
    const float* adj  = (const float*)d_in[5];
    const float* relk = (const float*)d_in[6];
    const float* sk   = (const float*)d_in[7];
    float* out = (float*)d_out;

    static int smem_set = 0;
    if (!smem_set) {
        cudaFuncSetAttribute(s_gemm, cudaFuncAttributeMaxDynamicSharedMemorySize,
                             SG_SMEM);
        cudaFuncSetAttribute(w_gemm, cudaFuncAttributeMaxDynamicSharedMemorySize,
                             WO_SMEM);
        cudaFuncSetAttribute(out_gemm, cudaFuncAttributeMaxDynamicSharedMemorySize,
                             WO_SMEM);
        smem_set = 1;
    }

    // 1) W[r] = E @ K[r]   (fp16 mma, fp32 acc)
    w_gemm<<<dim3(NN / 128, RR), 256, WO_SMEM>>>(emb, relk);
    // 2) Spart[z] = sum_r adj_r @ W_r over z's k-range  (no atomics)
    s_gemm<<<dim3(NN / BM, ZSPLIT), 256, SG_SMEM>>>(adj);
    // 3) S = sum_z Spart[z]
    reduce_kernel<<<NN * OO / (512 * 4), 512>>>();
    // 4) out = [he;te] @ SK + gather(S, idx)
    out_gemm<<<2 * BB / 128, 256, WO_SMEM>>>(he, te, hidx, tidx, sk, out);
}

// round 10
// speedup vs baseline: 1.3232x; 1.0956x over previous
#include <cuda_runtime.h>
#include <cuda_fp16.h>
#include <cstdint>

#define NN 4096   // nodes
#define DD 128    // embed dim
#define RR 8      // relations
#define OO 128    // out dim
#define BB 4096   // batch
#define ZSPLIT 8  // k-splits in s_gemm

// Scratch: W[r][n][o] = (E @ K[r])[n][o], fp16, 8 MB.
__device__ __half d_W16[RR * (size_t)NN * OO];
// Scratch: partial S per k-split, fp32, 16 MB.
__device__ float d_Spart[ZSPLIT * (size_t)NN * OO];
// Scratch: S[n][o] = sum_z Spart, fp32, 2 MB.
__device__ float d_S[(size_t)NN * OO];

// ---------------------------------------------------------------------------
// MMA helpers
// ---------------------------------------------------------------------------
__device__ __forceinline__ uint32_t smaddr(const void* p) {
    return (uint32_t)__cvta_generic_to_shared(p);
}
__device__ __forceinline__ void ldsm_x4(uint32_t (&r)[4], uint32_t addr) {
    asm volatile("ldmatrix.sync.aligned.m8n8.x4.shared.b16 {%0,%1,%2,%3}, [%4];"
        : "=r"(r[0]), "=r"(r[1]), "=r"(r[2]), "=r"(r[3]) : "r"(addr));
}
// x4 trans: lanes 0-15 rows k0..15 at col n0  -> r0,r1 (n8 frag #0)
//           lanes 16-31 rows k0..15 at col n0+8 -> r2,r3 (n8 frag #1)
__device__ __forceinline__ void ldsm_x4t(uint32_t (&r)[4], uint32_t addr) {
    asm volatile("ldmatrix.sync.aligned.m8n8.x4.trans.shared.b16 {%0,%1,%2,%3}, [%4];"
        : "=r"(r[0]), "=r"(r[1]), "=r"(r[2]), "=r"(r[3]) : "r"(addr));
}
__device__ __forceinline__ void mma_16816(float (&c)[4], const uint32_t (&a)[4],
                                          const uint32_t b0, const uint32_t b1) {
    asm volatile(
        "mma.sync.aligned.m16n8k16.row.col.f32.f16.f16.f32 "
        "{%0,%1,%2,%3}, {%4,%5,%6,%7}, {%8,%9}, {%0,%1,%2,%3};"
        : "+f"(c[0]), "+f"(c[1]), "+f"(c[2]), "+f"(c[3])
        : "r"(a[0]), "r"(a[1]), "r"(a[2]), "r"(a[3]), "r"(b0), "r"(b1));
}
__device__ __forceinline__ void cpa16(uint32_t s, const void* g) {
    asm volatile("cp.async.cg.shared.global [%0], [%1], 16;" :: "r"(s), "l"(g));
}
#define CPA_COMMIT() asm volatile("cp.async.commit_group;" ::: "memory")
#define CPA_WAIT0()  asm volatile("cp.async.wait_group 0;" ::: "memory")

// ---------------------------------------------------------------------------
// Single-shot MROWSx128x128 fp16 MMA core (w_gemm / out_gemm).
// A (MROWSx128 fp32 row-major), B (128x128 fp32 k-major) -> fp16 smem.
// 8 warps: wm = warp>>2 covers MROWS/2 rows, wn = warp&3 covers 32 cols.
// ---------------------------------------------------------------------------
#define STR 136                       // halves per smem row (128 + 8 pad)

template<int MROWS>
__device__ __forceinline__ void wo_core(
    const float* __restrict__ Ag, const float* __restrict__ Bg,
    char* dsm, float (&acc)[MROWS / 32][4][4])
{
    constexpr int MF = MROWS / 32;
    const int t = threadIdx.x;
    const uint32_t sb = smaddr(dsm);
    char* As = dsm;
    char* Bs = dsm + MROWS * STR * 2;
    const uint32_t AOFF = sb, BOFF = sb + MROWS * STR * 2;

#pragma unroll
    for (int j = 0; j < MROWS / 8; j++) {
        int id = t + j * 256;
        int row = id >> 5, c4 = id & 31;
        float4 v = *(const float4*)(Ag + (size_t)row * 128 + c4 * 4);
        __half2 h0 = __floats2half2_rn(v.x, v.y);
        __half2 h1 = __floats2half2_rn(v.z, v.w);
        uint2 u; u.x = *(uint32_t*)&h0; u.y = *(uint32_t*)&h1;
        *(uint2*)(As + row * STR * 2 + c4 * 8) = u;
    }
#pragma unroll
    for (int j = 0; j < 16; j++) {
        int id = t + j * 256;
        int row = id >> 5, c4 = id & 31;
        float4 v = *(const float4*)(Bg + (size_t)row * 128 + c4 * 4);
        __half2 h0 = __floats2half2_rn(v.x, v.y);
        __half2 h1 = __floats2half2_rn(v.z, v.w);
        uint2 u; u.x = *(uint32_t*)&h0; u.y = *(uint32_t*)&h1;
        *(uint2*)(Bs + row * STR * 2 + c4 * 8) = u;
    }
    __syncthreads();

    const int warp = t >> 5, lane = t & 31;
    const int wm = warp >> 2, wn = warp & 3;

    uint32_t a_off[MF], b_off[2];
#pragma unroll
    for (int mf = 0; mf < MF; mf++) {
        int row = wm * (MROWS / 2) + mf * 16 + (lane & 15);
        int col = ((lane >> 4) << 3);
        a_off[mf] = (uint32_t)(row * STR * 2 + col * 2);
    }
#pragma unroll
    for (int nf2 = 0; nf2 < 2; nf2++) {
        int row = (lane & 15);
        int col = wn * 32 + nf2 * 16 + ((lane >> 4) << 3);
        b_off[nf2] = (uint32_t)(row * STR * 2 + col * 2);
    }

#pragma unroll
    for (int ks = 0; ks < 8; ks++) {
        uint32_t af[MF][4], bf[2][4];
#pragma unroll
        for (int mf = 0; mf < MF; mf++)
            ldsm_x4(af[mf], AOFF + a_off[mf] + ks * 32);
#pragma unroll
        for (int nf2 = 0; nf2 < 2; nf2++)
            ldsm_x4t(bf[nf2], BOFF + b_off[nf2] + ks * 16 * STR * 2);
#pragma unroll
        for (int mf = 0; mf < MF; mf++)
#pragma unroll
            for (int nf = 0; nf < 4; nf++)
                mma_16816(acc[mf][nf], af[mf], bf[nf >> 1][(nf & 1) * 2],
                          bf[nf >> 1][(nf & 1) * 2 + 1]);
    }
}

// ---------------------------------------------------------------------------
// Kernel 1: W16[r] = fp16(E @ K[r]).  grid (32 m-tiles, 8 relations), 256 thr.
// ---------------------------------------------------------------------------
#define W_SMEM (2 * 128 * STR * 2)   // 69632 B

__global__ __launch_bounds__(256, 2) void w_gemm(
    const float* __restrict__ emb, const float* __restrict__ relk)
{
    extern __shared__ __align__(128) char dsm[];
    const int m0 = blockIdx.x * 128;
    const int r = blockIdx.y;

    float acc[4][4][4];
#pragma unroll
    for (int mf = 0; mf < 4; mf++)
#pragma unroll
        for (int nf = 0; nf < 4; nf++)
#pragma unroll
            for (int v = 0; v < 4; v++) acc[mf][nf][v] = 0.f;

    wo_core<128>(emb + (size_t)m0 * DD, relk + (size_t)r * DD * OO, dsm, acc);

    const int warp = threadIdx.x >> 5, lane = threadIdx.x & 31;
    const int wm = warp >> 2, wn = warp & 3;
    __half* Wr = d_W16 + (size_t)r * NN * OO;
    const int rbase = m0 + wm * 64 + (lane >> 2);
    const int cbase = wn * 32 + (lane & 3) * 2;
#pragma unroll
    for (int mf = 0; mf < 4; mf++)
#pragma unroll
        for (int nf = 0; nf < 4; nf++) {
            int rr = rbase + mf * 16, cc = cbase + nf * 8;
            *(__half2*)(Wr + (size_t)rr * OO + cc) =
                __floats2half2_rn(acc[mf][nf][0], acc[mf][nf][1]);
            *(__half2*)(Wr + (size_t)(rr + 8) * OO + cc) =
                __floats2half2_rn(acc[mf][nf][2], acc[mf][nf][3]);
        }
}

// ---------------------------------------------------------------------------
// Kernel 2: Spart[z][m][o] = sum_r sum_{k in z-range} adj[r,m,k] * W[r][k][o]
// grid (32 m-tiles, 8 z-splits) = 256 CTAs (single wave at occ 2), 256 thr.
// Double-buffered, cp.async B, x4t B fragments, no atomics.
// ---------------------------------------------------------------------------
#define BM 128
#define BK 64
#define KRANGE (NN / ZSPLIT)      // 512 k per CTA per relation
#define QITERS (RR * KRANGE / BK) // 64 chunks
#define ASTR (BK + 8)
#define BSTR (OO + 8)
#define A_STAGE (BM * ASTR * 2)   // 18432 B
#define B_STAGE (BK * BSTR * 2)   // 17408 B
#define SG_SMEM (2 * A_STAGE + 2 * B_STAGE)   // 71680 B

__global__ __launch_bounds__(256, 2) void s_gemm(const float* __restrict__ adj)
{
    extern __shared__ __align__(128) char dsm[];
    const uint32_t sb = smaddr(dsm);
    const int t = threadIdx.x;
    const int m0 = blockIdx.x * BM;
    const int z = blockIdx.y;
    const int kz = z * KRANGE;

    const uint32_t AOFF[2] = { sb, sb + A_STAGE };
    char* const ABASE[2] = { dsm, dsm + A_STAGE };
    const uint32_t BOFF[2] = { sb + 2 * A_STAGE, sb + 2 * A_STAGE + B_STAGE };

    const float* aptr[8]; uint32_t ast[8];
#pragma unroll
    for (int j = 0; j < 8; j++) {
        int id = t + j * 256;
        int arow = id >> 4, ac4 = id & 15;
        aptr[j] = adj + (size_t)(m0 + arow) * NN + kz + ac4 * 4;
        ast[j] = (uint32_t)(arow * ASTR * 2 + ac4 * 8);
    }
    const __half* bgp[4]; uint32_t bst[4];
#pragma unroll
    for (int j = 0; j < 4; j++) {
        int id = t + j * 256;
        int brow = id >> 4, bc8 = id & 15;
        bgp[j] = d_W16 + (size_t)(kz + brow) * OO + bc8 * 8;
        bst[j] = (uint32_t)(brow * BSTR * 2 + bc8 * 16);
    }

    const int warp = t >> 5, lane = t & 31;
    const int wm = warp >> 2, wn = warp & 3;

    float acc[4][4][4];
#pragma unroll
    for (int mf = 0; mf < 4; mf++)
#pragma unroll
        for (int nf = 0; nf < 4; nf++)
#pragma unroll
            for (int v = 0; v < 4; v++) acc[mf][nf][v] = 0.f;

    uint32_t a_off[4], b_off[2];
#pragma unroll
    for (int mf = 0; mf < 4; mf++) {
        int row = wm * 64 + mf * 16 + (lane & 15);
        int col = ((lane >> 4) << 3);
        a_off[mf] = (uint32_t)(row * ASTR * 2 + col * 2);
    }
#pragma unroll
    for (int nf2 = 0; nf2 < 2; nf2++) {
        int row = (lane & 15);
        int col = wn * 32 + nf2 * 16 + ((lane >> 4) << 3);
        b_off[nf2] = (uint32_t)(row * BSTR * 2 + col * 2);
    }

    // per-chunk uniform offsets: q -> (r = q>>3, kc = q&7)
    auto QA = [](int q) -> size_t {
        return ((size_t)(q >> 3) * (size_t)NN * NN) + (size_t)(q & 7) * BK;
    };
    auto QB = [](int q) -> size_t {
        return ((size_t)(q >> 3) * (size_t)NN * OO) + (size_t)(q & 7) * BK * OO;
    };

    float4 areg[8];

    // prologue: chunk 0 -> stage 0
#pragma unroll
    for (int j = 0; j < 8; j++) areg[j] = *(const float4*)aptr[j];
#pragma unroll
    for (int j = 0; j < 8; j++) {
        __half2 h0 = __floats2half2_rn(areg[j].x, areg[j].y);
        __half2 h1 = __floats2half2_rn(areg[j].z, areg[j].w);
        uint2 u; u.x = *(uint32_t*)&h0; u.y = *(uint32_t*)&h1;
        *(uint2*)(ABASE[0] + ast[j]) = u;
    }
#pragma unroll
    for (int j = 0; j < 4; j++) cpa16(BOFF[0] + bst[j], bgp[j]);
    CPA_COMMIT();
    {
        const size_t o1 = QA(1);
#pragma unroll
        for (int j = 0; j < 8; j++) areg[j] = *(const float4*)(aptr[j] + o1);
    }
    CPA_WAIT0();
    __syncthreads();

    for (int q = 0; q < QITERS; q++) {
        const int s = q & 1, ns = s ^ 1;

        if (q + 1 < QITERS) {
#pragma unroll
            for (int j = 0; j < 8; j++) {
                __half2 h0 = __floats2half2_rn(areg[j].x, areg[j].y);
                __half2 h1 = __floats2half2_rn(areg[j].z, areg[j].w);
                uint2 u; u.x = *(uint32_t*)&h0; u.y = *(uint32_t*)&h1;
                *(uint2*)(ABASE[ns] + ast[j]) = u;
            }
            const size_t ob = QB(q + 1);
#pragma unroll
            for (int j = 0; j < 4; j++) cpa16(BOFF[ns] + bst[j], bgp[j] + ob);
            CPA_COMMIT();
        }
        if (q + 2 < QITERS) {
            const size_t oa = QA(q + 2);
#pragma unroll
            for (int j = 0; j < 8; j++) areg[j] = *(const float4*)(aptr[j] + oa);
        }

#pragma unroll
        for (int ks = 0; ks < 4; ks++) {
            uint32_t af[4][4], bf[2][4];
#pragma unroll
            for (int mf = 0; mf < 4; mf++)
                ldsm_x4(af[mf], AOFF[s] + a_off[mf] + ks * 32);
#pragma unroll
            for (int nf2 = 0; nf2 < 2; nf2++)
                ldsm_x4t(bf[nf2], BOFF[s] + b_off[nf2] + ks * 16 * BSTR * 2);
#pragma unroll
            for (int mf = 0; mf < 4; mf++)
#pragma unroll
                for (int nf = 0; nf < 4; nf++)
                    mma_16816(acc[mf][nf], af[mf], bf[nf >> 1][(nf & 1) * 2],
                              bf[nf >> 1][(nf & 1) * 2 + 1]);
        }

        if (q + 1 < QITERS) CPA_WAIT0();
        __syncthreads();
    }

    float* Sp = d_Spart + (size_t)z * NN * OO;
    const int rbase = m0 + wm * 64 + (lane >> 2);
    const int cbase = wn * 32 + (lane & 3) * 2;
#pragma unroll
    for (int mf = 0; mf < 4; mf++)
#pragma unroll
        for (int nf = 0; nf < 4; nf++) {
            int rr = rbase + mf * 16, cc = cbase + nf * 8;
            *(float2*)(Sp + (size_t)rr * OO + cc) =
                make_float2(acc[mf][nf][0], acc[mf][nf][1]);
            *(float2*)(Sp + (size_t)(rr + 8) * OO + cc) =
                make_float2(acc[mf][nf][2], acc[mf][nf][3]);
        }
}

// ---------------------------------------------------------------------------
// Kernel 3: S = sum_z Spart[z].  grid 256, 512 threads, float4 each.
// ---------------------------------------------------------------------------
__global__ __launch_bounds__(512) void reduce_kernel()
{
    const size_t i = (size_t)blockIdx.x * 512 + threadIdx.x;
    const float4* p = (const float4*)d_Spart + i;
    float4 s = p[0];
#pragma unroll
    for (int zz = 1; zz < ZSPLIT; zz++) {
        float4 v = p[(size_t)zz * (NN * OO / 4)];
        s.x += v.x; s.y += v.y; s.z += v.z; s.w += v.w;
    }
    ((float4*)d_S)[i] = s;
}

// ---------------------------------------------------------------------------
// Kernel 4: out[m][o] = ([he;te] @ SK)[m][o] + S[idx[m]][o]
// 32-row tiles: grid 256 CTAs, 256 threads, high occupancy.
// ---------------------------------------------------------------------------
#define O_SMEM ((32 + 128) * STR * 2)   // 43520 B

__global__ __launch_bounds__(256) void out_gemm(
    const float* __restrict__ head_e, const float* __restrict__ tail_e,
    const int* __restrict__ head_idx, const int* __restrict__ tail_idx,
    const float* __restrict__ sk, float* __restrict__ out)
{
    extern __shared__ __align__(128) char dsm[];
    const int m0 = blockIdx.x * 32;
    const int branch = (m0 >= BB);
    const int mloc0 = branch ? m0 - BB : m0;
    const float* e = (branch ? tail_e : head_e) + (size_t)mloc0 * DD;
    const int* idx = branch ? tail_idx : head_idx;

    float acc[1][4][4];
#pragma unroll
    for (int nf = 0; nf < 4; nf++)
#pragma unroll
        for (int v = 0; v < 4; v++) acc[0][nf][v] = 0.f;

    wo_core<32>(e, sk, dsm, acc);

    const int warp = threadIdx.x >> 5, lane = threadIdx.x & 31;
    const int wm = warp >> 2, wn = warp & 3;
    const int rloc = mloc0 + wm * 16 + (lane >> 2);
    const int cbase = wn * 32 + (lane & 3) * 2;

    int i0 = idx[rloc], i1 = idx[rloc + 8];
    const float* S0 = d_S + (size_t)i0 * OO;
    const float* S1 = d_S + (size_t)i1 * OO;
    float* o0 = out + ((size_t)branch * BB + rloc) * OO;
    float* o1 = o0 + 8 * OO;
#pragma unroll
    for (int nf = 0; nf < 4; nf++) {
        int cc = cbase + nf * 8;
        float2 s0 = *(const float2*)(S0 + cc);
        float2 s1 = *(const float2*)(S1 + cc);
        *(float2*)(o0 + cc) = make_float2(acc[0][nf][0] + s0.x,
                                          acc[0][nf][1] + s0.y);
        *(float2*)(o1 + cc) = make_float2(acc[0][nf][2] + s1.x,
                                          acc[0][nf][3] + s1.y);
    }
}

// ---------------------------------------------------------------------------
extern "C" void kernel_launch(void* const* d_in, const int* in_sizes, int n_in,
                              void* d_out, int out_size)
{
    const float* emb  = (const float*)d_in[0];
    const int*   hidx = (const int*)  d_in[1];
    const float* he   = (const float*)d_in[2];
    const int*   tidx = (const int*)  d_in[3];
    const float* te   = (const float*)d_in[4];
    const float* adj  = (const float*)d_in[5];
    const float* relk = (const float*)d_in[6];
    const float* sk   = (const float*)d_in[7];
    float* out = (float*)d_out;

    cudaFuncSetAttribute(s_gemm, cudaFuncAttributeMaxDynamicSharedMemorySize, SG_SMEM);
    cudaFuncSetAttribute(w_gemm, cudaFuncAttributeMaxDynamicSharedMemorySize, W_SMEM);
    cudaFuncSetAttribute(out_gemm, cudaFuncAttributeMaxDynamicSharedMemorySize, O_SMEM);

    // 1) W[r] = E @ K[r]   (fp16 mma, fp32 acc)
    w_gemm<<<dim3(NN / 128, RR), 256, W_SMEM>>>(emb, relk);
    // 2) Spart[z] = sum_r adj_r @ W_r over z's k-range  (no atomics)
    s_gemm<<<dim3(NN / BM, ZSPLIT), 256, SG_SMEM>>>(adj);
    // 3) S = sum_z Spart[z]
    reduce_kernel<<<NN * OO / (512 * 4), 512>>>();
    // 4) out = [he;te] @ SK + gather(S, idx)
    out_gemm<<<2 * BB / 32, 256, O_SMEM>>>(he, te, hidx, tidx, sk, out);
}